// round 6
// baseline (speedup 1.0000x reference)
#include <cuda_runtime.h>
#include <math.h>

#define BB 64
#define NN 128

// scratch for intermediate coors/vel between layers (no allocs allowed)
__device__ float g_c0[BB*NN*2];
__device__ float g_v0[BB*NN*2];
__device__ float g_c1[BB*NN*2];
__device__ float g_v1[BB*NN*2];

union F2U { float2 f; unsigned long long u; };

__device__ __forceinline__ float2 ffma2(float2 a, float2 b, float2 c) {
    F2U A, B, C, R;
    A.f = a; B.f = b; C.f = c;
    asm("fma.rn.f32x2 %0, %1, %2, %3;" : "=l"(R.u) : "l"(A.u), "l"(B.u), "l"(C.u));
    return R.f;
}
__device__ __forceinline__ float2 fmul2(float2 a, float2 b) {
    F2U A, B, R;
    A.f = a; B.f = b;
    asm("mul.rn.f32x2 %0, %1, %2;" : "=l"(R.u) : "l"(A.u), "l"(B.u));
    return R.f;
}

__device__ __forceinline__ float tanhaf(float x) {
    float r; asm("tanh.approx.f32 %0, %1;" : "=f"(r) : "f"(x)); return r;
}

// input h = x/2 (accumulated with pre-scaled weights). returns silu(x) = h + h*tanh(h).
__device__ __forceinline__ float2 silu2_pre(float2 h) {
    float t0 = tanhaf(h.x);
    float t1 = tanhaf(h.y);
    return ffma2(h, make_float2(t0, t1), h);
}
// plain silu on x
__device__ __forceinline__ float2 silu2(float2 x) {
    float2 h = fmul2(x, make_float2(0.5f, 0.5f));
    return silu2_pre(h);
}

__device__ __forceinline__ float seluf(float x) {
    const float scale = 1.0507009873554805f;
    const float alpha = 1.6732632423543772f;
    return x > 0.0f ? scale * x : scale * alpha * expm1f(x);
}

__global__ __launch_bounds__(128, 5)
void egnn_layer_kernel(const float* __restrict__ t,
                       const float* __restrict__ cin,
                       const float* __restrict__ vin,
                       float* __restrict__ cout,
                       float* __restrict__ vout,
                       const float* __restrict__ We1,
                       const float* __restrict__ be1,
                       const float* __restrict__ We2,
                       const float* __restrict__ be2,
                       const float* __restrict__ Wc1,
                       const float* __restrict__ bc1,
                       const float* __restrict__ Wc2,
                       const float* __restrict__ bc2,
                       const float* __restrict__ Wv,
                       const float* __restrict__ bv,
                       int l)
{
    // block = (batch, 4 i's). warp w owns i = ibase + w.
    // each thread handles 4 edges for its i: packed pairs A=(ln, ln+32), B=(ln+64, ln+96).
    __shared__ float4 sUV[16];      // {u,u,v,v}  (x0.5)
    __shared__ float4 sWC[16];      // {w,w,c,c}  (x0.5, c includes be1)
    __shared__ float2 sbe2[16];     // dup be2    (x0.5)
    __shared__ float4 sWe2d[128];   // We2 dup pairs (x0.5): [n*8+cp] = {w(n,2cp)x2, w(n,2cp+1)x2}
    __shared__ float2 sWc1s[1024];  // Wc1 dup singles (x0.5): [c*16+n] = {w(n,c)x2}
    __shared__ float4 sbcw[64];     // per channel: {bc1*0.5, bc1*0.5, Wc2, Wc2}
    __shared__ float2 scj2[NN];
    __shared__ float  stj[NN];

    const int tid   = threadIdx.x;
    const int wid   = tid >> 5;
    const int ln    = tid & 31;
    const int bb    = blockIdx.x >> 5;
    const int ibase = (blockIdx.x & 31) * 4;
    const int i     = ibase + wid;

    // ---- setup: fold + duplicate + prescale weights into shared ----
    const float* we1 = We1 + l * 128;
    if (tid < 16) {
        float u = 0.5f * (we1[tid] + we1[16 + tid] + we1[32 + tid]);
        float v = 0.5f * (we1[48 + tid] + we1[64 + tid] + we1[80 + tid]);
        float w = 0.5f * we1[96 + tid];
        float c = 0.5f * (we1[112 + tid] + be1[l * 16 + tid]);
        sUV[tid] = make_float4(u, u, v, v);
        sWC[tid] = make_float4(w, w, c, c);
        float b2 = 0.5f * be2[l * 16 + tid];
        sbe2[tid] = make_float2(b2, b2);
    } else if (tid < 80) {
        int k = tid - 16;
        float b = 0.5f * bc1[l * 64 + k];
        float w = Wc2[l * 64 + k];
        sbcw[k] = make_float4(b, b, w, w);
    }
    {
        int n = tid >> 3, cp = tid & 7;
        float a = 0.5f * We2[l * 256 + n * 16 + 2 * cp];
        float b = 0.5f * We2[l * 256 + n * 16 + 2 * cp + 1];
        sWe2d[tid] = make_float4(a, a, b, b);
    }
    #pragma unroll
    for (int idx = tid; idx < 1024; idx += 128) {
        int c = idx >> 4, n = idx & 15;
        float w = 0.5f * Wc1[l * 1024 + n * 64 + c];
        sWc1s[idx] = make_float2(w, w);
    }
    {
        const float2* c2 = (const float2*)(cin + bb * NN * 2);
        scj2[tid] = c2[tid];            // 128 threads, 128 nodes
        stj[tid]  = t[bb * NN + tid];
    }
    __syncthreads();

    // ---- per-pair: layer1 + MLP2 -> q (K-split to bound registers) ----
    float2 q_a[16], q_b[16];
    #pragma unroll
    for (int pp = 0; pp < 2; ++pp) {
        const int j0 = ln + (pp ? 64 : 0);
        const int j1 = j0 + 32;
        float2* q = pp ? q_b : q_a;

        const float ti = stj[i];
        const float2 ci = scj2[i];
        const float2 cj0 = scj2[j0];
        const float2 cj1 = scj2[j1];
        const float2 ti2 = make_float2(ti, ti);
        const float2 tj2 = make_float2(stj[j0], stj[j1]);
        const float2 dx2 = make_float2(ci.x - cj0.x, ci.x - cj1.x);
        const float2 dy2 = make_float2(ci.y - cj0.y, ci.y - cj1.y);
        const float2 d2  = ffma2(dx2, dx2, fmul2(dy2, dy2));

        // acc = m/2 accumulates across both K-halves
        float2 acc[16];
        #pragma unroll
        for (int c = 0; c < 16; ++c) acc[c] = sbe2[c];

        #pragma unroll
        for (int hk = 0; hk < 2; ++hk) {
            float2 x1[8];
            #pragma unroll
            for (int k = 0; k < 8; ++k) {
                float4 uv = sUV[hk * 8 + k];
                float4 wc = sWC[hk * 8 + k];
                float2 h = ffma2(ti2, make_float2(uv.x, uv.y),
                          ffma2(tj2, make_float2(uv.z, uv.w),
                          ffma2(d2,  make_float2(wc.x, wc.y),
                                     make_float2(wc.z, wc.w))));
                x1[k] = silu2_pre(h);
            }
            #pragma unroll
            for (int cp = 0; cp < 8; ++cp) {
                float2 a0 = acc[2 * cp];
                float2 a1 = acc[2 * cp + 1];
                #pragma unroll
                for (int n = 0; n < 8; ++n) {
                    float4 w = sWe2d[(hk * 8 + n) * 8 + cp];
                    a0 = ffma2(x1[n], make_float2(w.x, w.y), a0);
                    a1 = ffma2(x1[n], make_float2(w.z, w.w), a1);
                }
                acc[2 * cp]     = a0;
                acc[2 * cp + 1] = a1;
            }
        }
        #pragma unroll
        for (int c = 0; c < 16; ++c) {
            q[c] = silu2(silu2_pre(acc[c]));
        }
    }

    // ---- MLP3 joint over both pairs, one channel per iter (4 acc regs) ----
    const float bc2l = bc2[l];
    float2 wsa = make_float2(bc2l, bc2l);
    float2 wsb = make_float2(bc2l, bc2l);
    #pragma unroll 4
    for (int c = 0; c < 64; ++c) {
        float4 bw = sbcw[c];
        float2 aa = make_float2(bw.x, bw.y);
        float2 ba = aa;
        #pragma unroll
        for (int n = 0; n < 16; ++n) {
            float2 w = sWc1s[c * 16 + n];
            aa = ffma2(q_a[n], w, aa);
            ba = ffma2(q_b[n], w, ba);
        }
        float2 wc = make_float2(bw.z, bw.w);
        wsa = ffma2(silu2_pre(aa), wc, wsa);
        wsb = ffma2(silu2_pre(ba), wc, wsb);
    }

    // ---- agg: recompute rel coords from shared, accumulate, warp-reduce ----
    float ax, ay;
    const float2 ci = scj2[i];
    {
        const float2 cj0 = scj2[ln];
        const float2 cj1 = scj2[ln + 32];
        const float2 cj2 = scj2[ln + 64];
        const float2 cj3 = scj2[ln + 96];
        float2 dxa = make_float2(ci.x - cj0.x, ci.x - cj1.x);
        float2 dya = make_float2(ci.y - cj0.y, ci.y - cj1.y);
        float2 dxb = make_float2(ci.x - cj2.x, ci.x - cj3.x);
        float2 dyb = make_float2(ci.y - cj2.y, ci.y - cj3.y);
        float2 ax2 = ffma2(wsb, dxb, fmul2(wsa, dxa));
        float2 ay2 = ffma2(wsb, dyb, fmul2(wsa, dya));
        ax = ax2.x + ax2.y;
        ay = ay2.x + ay2.y;
    }
    #pragma unroll
    for (int off = 16; off > 0; off >>= 1) {
        ax += __shfl_down_sync(0xFFFFFFFFu, ax, off);
        ay += __shfl_down_sync(0xFFFFFFFFu, ay, off);
    }

    if (ln == 0) {
        float ti  = stj[i];
        float wv  = Wv[l * 3] + Wv[l * 3 + 1] + Wv[l * 3 + 2];
        float phi = fmaf(ti, wv, bv[l]);
        float vx = vin[(bb * NN + i) * 2];
        float vy = vin[(bb * NN + i) * 2 + 1];
        float nvx = fmaf(phi, vx, ax);
        float nvy = fmaf(phi, vy, ay);
        float ncx = ci.x + nvx;
        float ncy = ci.y + nvy;
        cout[(bb * NN + i) * 2]     = seluf(ncx);
        cout[(bb * NN + i) * 2 + 1] = seluf(ncy);
        vout[(bb * NN + i) * 2]     = seluf(nvx);
        vout[(bb * NN + i) * 2 + 1] = seluf(nvy);
    }
}

__global__ void egnn_head_kernel(const float* __restrict__ cin,
                                 const float* __restrict__ vin,
                                 const float* __restrict__ Wconv1,
                                 const float* __restrict__ bconv1,
                                 const float* __restrict__ Wconv2,
                                 const float* __restrict__ bconv2,
                                 float* __restrict__ out)
{
    int idx = blockIdx.x * blockDim.x + threadIdx.x;
    if (idx >= BB * NN) return;

    float x0 = seluf(cin[idx * 2]);
    float x1 = seluf(cin[idx * 2 + 1]);
    float x2 = seluf(vin[idx * 2]);
    float x3 = seluf(vin[idx * 2 + 1]);

    float y0 = bconv2[0], y1 = bconv2[1], y2 = bconv2[2], y3 = bconv2[3];
    #pragma unroll
    for (int o = 0; o < 32; o++) {
        float h = bconv1[o];
        h = fmaf(x0, Wconv1[o * 4 + 0], h);
        h = fmaf(x1, Wconv1[o * 4 + 1], h);
        h = fmaf(x2, Wconv1[o * 4 + 2], h);
        h = fmaf(x3, Wconv1[o * 4 + 3], h);
        h = seluf(h);
        y0 = fmaf(h, Wconv2[0 * 32 + o], y0);
        y1 = fmaf(h, Wconv2[1 * 32 + o], y1);
        y2 = fmaf(h, Wconv2[2 * 32 + o], y2);
        y3 = fmaf(h, Wconv2[3 * 32 + o], y3);
    }
    out[idx * 2]                   = y0;
    out[idx * 2 + 1]               = y1;
    out[BB * NN * 2 + idx * 2]     = y2;
    out[BB * NN * 2 + idx * 2 + 1] = y3;
}

extern "C" void kernel_launch(void* const* d_in, const int* in_sizes, int n_in,
                              void* d_out, int out_size)
{
    const float* t      = (const float*)d_in[0];
    const float* coors  = (const float*)d_in[1];
    const float* vel    = (const float*)d_in[2];
    const float* We1    = (const float*)d_in[3];
    const float* be1    = (const float*)d_in[4];
    const float* We2    = (const float*)d_in[5];
    const float* be2    = (const float*)d_in[6];
    const float* Wc1    = (const float*)d_in[7];
    const float* bc1    = (const float*)d_in[8];
    const float* Wc2    = (const float*)d_in[9];
    const float* bc2    = (const float*)d_in[10];
    const float* Wv     = (const float*)d_in[11];
    const float* bv     = (const float*)d_in[12];
    const float* Wconv1 = (const float*)d_in[13];
    const float* bconv1 = (const float*)d_in[14];
    const float* Wconv2 = (const float*)d_in[15];
    const float* bconv2 = (const float*)d_in[16];
    float* out = (float*)d_out;

    float *c0, *v0, *c1, *v1;
    cudaGetSymbolAddress((void**)&c0, g_c0);
    cudaGetSymbolAddress((void**)&v0, g_v0);
    cudaGetSymbolAddress((void**)&c1, g_c1);
    cudaGetSymbolAddress((void**)&v1, g_v1);

    dim3 grid(BB * 32);   // 2048 blocks: (batch, group of 4 i's), warp-per-i
    dim3 blk(128);
    egnn_layer_kernel<<<grid, blk>>>(t, coors, vel, c0, v0,
                                     We1, be1, We2, be2, Wc1, bc1, Wc2, bc2,
                                     Wv, bv, 0);
    egnn_layer_kernel<<<grid, blk>>>(t, c0, v0, c1, v1,
                                     We1, be1, We2, be2, Wc1, bc1, Wc2, bc2,
                                     Wv, bv, 1);
    egnn_head_kernel<<<(BB * NN + 127) / 128, 128>>>(c1, v1, Wconv1, bconv1,
                                                     Wconv2, bconv2, out);
}

// round 7
// speedup vs baseline: 1.5943x; 1.5943x over previous
#include <cuda_runtime.h>
#include <math.h>

#define BB 64
#define NN 128

// scratch for intermediate coors/vel between layers (no allocs allowed)
__device__ float g_c0[BB*NN*2];
__device__ float g_v0[BB*NN*2];
__device__ float g_c1[BB*NN*2];
__device__ float g_v1[BB*NN*2];

union F2U { float2 f; unsigned long long u; };

__device__ __forceinline__ float2 ffma2(float2 a, float2 b, float2 c) {
    F2U A, B, C, R;
    A.f = a; B.f = b; C.f = c;
    asm("fma.rn.f32x2 %0, %1, %2, %3;" : "=l"(R.u) : "l"(A.u), "l"(B.u), "l"(C.u));
    return R.f;
}
__device__ __forceinline__ float2 fmul2(float2 a, float2 b) {
    F2U A, B, R;
    A.f = a; B.f = b;
    asm("mul.rn.f32x2 %0, %1, %2;" : "=l"(R.u) : "l"(A.u), "l"(B.u));
    return R.f;
}

__device__ __forceinline__ float tanhaf(float x) {
    float r; asm("tanh.approx.f32 %0, %1;" : "=f"(r) : "f"(x)); return r;
}

// input h = x/2 (accumulated with pre-scaled weights). returns silu(x) = h + h*tanh(h).
__device__ __forceinline__ float2 silu2_pre(float2 h) {
    float t0 = tanhaf(h.x);
    float t1 = tanhaf(h.y);
    return ffma2(h, make_float2(t0, t1), h);
}
// plain silu on x
__device__ __forceinline__ float2 silu2(float2 x) {
    float2 h = fmul2(x, make_float2(0.5f, 0.5f));
    return silu2_pre(h);
}

__device__ __forceinline__ float seluf(float x) {
    const float scale = 1.0507009873554805f;
    const float alpha = 1.6732632423543772f;
    return x > 0.0f ? scale * x : scale * alpha * expm1f(x);
}

__global__ __launch_bounds__(128, 4)
void egnn_layer_kernel(const float* __restrict__ t,
                       const float* __restrict__ cin,
                       const float* __restrict__ vin,
                       float* __restrict__ cout,
                       float* __restrict__ vout,
                       const float* __restrict__ We1,
                       const float* __restrict__ be1,
                       const float* __restrict__ We2,
                       const float* __restrict__ be2,
                       const float* __restrict__ Wc1,
                       const float* __restrict__ bc1,
                       const float* __restrict__ Wc2,
                       const float* __restrict__ bc2,
                       const float* __restrict__ Wv,
                       const float* __restrict__ bv,
                       int l)
{
    // block = (batch b, group of 4 i's). threads 0-63 handle (i0,i1); 64-127 handle (i2,i3).
    // each thread processes the j-pair (lt, lt+64) packed in f32x2 for TWO i-contexts.
    __shared__ float4 sUV[16];      // {u,u,v,v}  (x0.5)
    __shared__ float4 sWC[16];      // {w,w,c,c}  (x0.5, c includes be1)
    __shared__ float2 sbe2[16];     // dup be2    (x0.5)
    __shared__ float4 sWe2d[128];   // We2 dup pairs (x0.5): [n*8+cp]
    __shared__ float4 sWc1d[512];   // Wc1 dup pairs (x0.5): [n*32+c]
    __shared__ float2 sbc1d[64];    // dup bc1    (x0.5)
    __shared__ float4 sWc2d[32];    // dup Wc2 pairs (unscaled)
    __shared__ float2 scj2[NN];
    __shared__ float  stj[NN];
    __shared__ float4 sred[4];      // per-warp {ax_a, ay_a, ax_b, ay_b}

    const int tid   = threadIdx.x;
    const int half  = tid >> 6;
    const int lt    = tid & 63;
    const int bb    = blockIdx.x >> 5;
    const int ibase = (blockIdx.x & 31) * 4;
    const int ia    = ibase + half * 2;
    const int ib    = ia + 1;

    // ---- setup: fold + duplicate + prescale weights into shared ----
    const float* we1 = We1 + l * 128;
    if (tid < 16) {
        float u = 0.5f * (we1[tid] + we1[16 + tid] + we1[32 + tid]);
        float v = 0.5f * (we1[48 + tid] + we1[64 + tid] + we1[80 + tid]);
        float w = 0.5f * we1[96 + tid];
        float c = 0.5f * (we1[112 + tid] + be1[l * 16 + tid]);
        sUV[tid] = make_float4(u, u, v, v);
        sWC[tid] = make_float4(w, w, c, c);
        float b2 = 0.5f * be2[l * 16 + tid];
        sbe2[tid] = make_float2(b2, b2);
    } else if (tid < 80) {
        int k = tid - 16;
        float b = 0.5f * bc1[l * 64 + k];
        sbc1d[k] = make_float2(b, b);
    } else if (tid < 112) {
        int k = tid - 80;
        float a = Wc2[l * 64 + 2 * k];
        float b = Wc2[l * 64 + 2 * k + 1];
        sWc2d[k] = make_float4(a, a, b, b);
    }
    {
        int n = tid >> 3, cp = tid & 7;
        float a = 0.5f * We2[l * 256 + n * 16 + 2 * cp];
        float b = 0.5f * We2[l * 256 + n * 16 + 2 * cp + 1];
        sWe2d[tid] = make_float4(a, a, b, b);
    }
    #pragma unroll
    for (int idx = tid; idx < 512; idx += 128) {
        int n = idx >> 5, c = idx & 31;
        float a = 0.5f * Wc1[l * 1024 + n * 64 + 2 * c];
        float b = 0.5f * Wc1[l * 1024 + n * 64 + 2 * c + 1];
        sWc1d[idx] = make_float4(a, a, b, b);
    }
    {
        const float2* c2 = (const float2*)(cin + bb * NN * 2);
        scj2[tid] = c2[tid];
        stj[tid]  = t[bb * NN + tid];
    }
    __syncthreads();

    const int j0 = lt, j1 = lt + 64;

    // ---- layer1 + MLP2, joint over both contexts, K-split for liveness ----
    float2 q_a[16], q_b[16];     // start life as m/2 accumulators
    {
        const float2 cj0 = scj2[j0];
        const float2 cj1 = scj2[j1];
        const float2 tj2 = make_float2(stj[j0], stj[j1]);
        const float ti_a = stj[ia], ti_b = stj[ib];
        const float2 cia = scj2[ia], cib = scj2[ib];
        const float2 tia2 = make_float2(ti_a, ti_a);
        const float2 tib2 = make_float2(ti_b, ti_b);
        float2 dxa = make_float2(cia.x - cj0.x, cia.x - cj1.x);
        float2 dya = make_float2(cia.y - cj0.y, cia.y - cj1.y);
        float2 dxb = make_float2(cib.x - cj0.x, cib.x - cj1.x);
        float2 dyb = make_float2(cib.y - cj0.y, cib.y - cj1.y);
        const float2 d2a = ffma2(dxa, dxa, fmul2(dya, dya));
        const float2 d2b = ffma2(dxb, dxb, fmul2(dyb, dyb));

        #pragma unroll
        for (int c = 0; c < 16; ++c) { q_a[c] = sbe2[c]; q_b[c] = sbe2[c]; }

        #pragma unroll
        for (int hk = 0; hk < 2; ++hk) {
            float2 x1a[8], x1b[8];
            #pragma unroll
            for (int k = 0; k < 8; ++k) {
                float4 uv = sUV[hk * 8 + k];
                float4 wc = sWC[hk * 8 + k];
                float2 base = ffma2(tj2, make_float2(uv.z, uv.w),
                                    make_float2(wc.z, wc.w));
                float2 ha = ffma2(tia2, make_float2(uv.x, uv.y),
                           ffma2(d2a, make_float2(wc.x, wc.y), base));
                float2 hb = ffma2(tib2, make_float2(uv.x, uv.y),
                           ffma2(d2b, make_float2(wc.x, wc.y), base));
                x1a[k] = silu2_pre(ha);
                x1b[k] = silu2_pre(hb);
            }
            #pragma unroll
            for (int cp = 0; cp < 8; ++cp) {
                float2 a0 = q_a[2 * cp], a1 = q_a[2 * cp + 1];
                float2 b0 = q_b[2 * cp], b1 = q_b[2 * cp + 1];
                #pragma unroll
                for (int n = 0; n < 8; ++n) {
                    float4 w = sWe2d[(hk * 8 + n) * 8 + cp];
                    float2 wlo = make_float2(w.x, w.y);
                    float2 whi = make_float2(w.z, w.w);
                    a0 = ffma2(x1a[n], wlo, a0);
                    a1 = ffma2(x1a[n], whi, a1);
                    b0 = ffma2(x1b[n], wlo, b0);
                    b1 = ffma2(x1b[n], whi, b1);
                }
                q_a[2 * cp] = a0; q_a[2 * cp + 1] = a1;
                q_b[2 * cp] = b0; q_b[2 * cp + 1] = b1;
            }
        }
        #pragma unroll
        for (int c = 0; c < 16; ++c) {
            q_a[c] = silu2(silu2_pre(q_a[c]));   // inner uses m/2 accum, outer plain
            q_b[c] = silu2(silu2_pre(q_b[c]));
        }
    }

    // ---- MLP3 joint over both contexts: weight LDS amortized x4 edges ----
    const float bc2l = bc2[l];
    float2 wsa = make_float2(bc2l, bc2l);
    float2 wsb = make_float2(bc2l, bc2l);
    #pragma unroll 4
    for (int c = 0; c < 32; ++c) {
        float2 bi0 = sbc1d[2 * c];
        float2 bi1 = sbc1d[2 * c + 1];
        float2 aa0 = bi0, aa1 = bi1;
        float2 ba0 = bi0, ba1 = bi1;
        #pragma unroll
        for (int n = 0; n < 16; ++n) {
            float4 w = sWc1d[n * 32 + c];
            float2 wlo = make_float2(w.x, w.y);
            float2 whi = make_float2(w.z, w.w);
            aa0 = ffma2(q_a[n], wlo, aa0);
            aa1 = ffma2(q_a[n], whi, aa1);
            ba0 = ffma2(q_b[n], wlo, ba0);
            ba1 = ffma2(q_b[n], whi, ba1);
        }
        float4 wc2 = sWc2d[c];
        float2 w0 = make_float2(wc2.x, wc2.y);
        float2 w1 = make_float2(wc2.z, wc2.w);
        wsa = ffma2(silu2_pre(aa0), w0, wsa);
        wsa = ffma2(silu2_pre(aa1), w1, wsa);
        wsb = ffma2(silu2_pre(ba0), w0, wsb);
        wsb = ffma2(silu2_pre(ba1), w1, wsb);
    }

    // ---- agg: recompute rel coords from shared, accumulate, reduce ----
    float axa, aya, axb, ayb;
    {
        const float2 cj0 = scj2[j0];
        const float2 cj1 = scj2[j1];
        const float2 cia = scj2[ia], cib = scj2[ib];
        float2 dxa = make_float2(cia.x - cj0.x, cia.x - cj1.x);
        float2 dya = make_float2(cia.y - cj0.y, cia.y - cj1.y);
        float2 dxb = make_float2(cib.x - cj0.x, cib.x - cj1.x);
        float2 dyb = make_float2(cib.y - cj0.y, cib.y - cj1.y);
        float2 axa2 = fmul2(wsa, dxa);
        float2 aya2 = fmul2(wsa, dya);
        float2 axb2 = fmul2(wsb, dxb);
        float2 ayb2 = fmul2(wsb, dyb);
        axa = axa2.x + axa2.y;
        aya = aya2.x + aya2.y;
        axb = axb2.x + axb2.y;
        ayb = ayb2.x + ayb2.y;
    }
    #pragma unroll
    for (int off = 16; off > 0; off >>= 1) {
        axa += __shfl_down_sync(0xFFFFFFFFu, axa, off);
        aya += __shfl_down_sync(0xFFFFFFFFu, aya, off);
        axb += __shfl_down_sync(0xFFFFFFFFu, axb, off);
        ayb += __shfl_down_sync(0xFFFFFFFFu, ayb, off);
    }
    const int wid = tid >> 5;
    if ((tid & 31) == 0) sred[wid] = make_float4(axa, aya, axb, ayb);
    __syncthreads();

    if (tid < 4) {
        const int i = ibase + tid;
        const int w0 = (tid >> 1) * 2;
        float AX, AY;
        if ((tid & 1) == 0) {
            AX = sred[w0].x + sred[w0 + 1].x;
            AY = sred[w0].y + sred[w0 + 1].y;
        } else {
            AX = sred[w0].z + sred[w0 + 1].z;
            AY = sred[w0].w + sred[w0 + 1].w;
        }
        float ti  = stj[i];
        float2 ci = scj2[i];
        float wv  = Wv[l * 3] + Wv[l * 3 + 1] + Wv[l * 3 + 2];
        float phi = fmaf(ti, wv, bv[l]);
        float vx = vin[(bb * NN + i) * 2];
        float vy = vin[(bb * NN + i) * 2 + 1];
        float nvx = fmaf(phi, vx, AX);
        float nvy = fmaf(phi, vy, AY);
        float ncx = ci.x + nvx;
        float ncy = ci.y + nvy;
        cout[(bb * NN + i) * 2]     = seluf(ncx);
        cout[(bb * NN + i) * 2 + 1] = seluf(ncy);
        vout[(bb * NN + i) * 2]     = seluf(nvx);
        vout[(bb * NN + i) * 2 + 1] = seluf(nvy);
    }
}

__global__ void egnn_head_kernel(const float* __restrict__ cin,
                                 const float* __restrict__ vin,
                                 const float* __restrict__ Wconv1,
                                 const float* __restrict__ bconv1,
                                 const float* __restrict__ Wconv2,
                                 const float* __restrict__ bconv2,
                                 float* __restrict__ out)
{
    int idx = blockIdx.x * blockDim.x + threadIdx.x;
    if (idx >= BB * NN) return;

    float x0 = seluf(cin[idx * 2]);
    float x1 = seluf(cin[idx * 2 + 1]);
    float x2 = seluf(vin[idx * 2]);
    float x3 = seluf(vin[idx * 2 + 1]);

    float y0 = bconv2[0], y1 = bconv2[1], y2 = bconv2[2], y3 = bconv2[3];
    #pragma unroll
    for (int o = 0; o < 32; o++) {
        float h = bconv1[o];
        h = fmaf(x0, Wconv1[o * 4 + 0], h);
        h = fmaf(x1, Wconv1[o * 4 + 1], h);
        h = fmaf(x2, Wconv1[o * 4 + 2], h);
        h = fmaf(x3, Wconv1[o * 4 + 3], h);
        h = seluf(h);
        y0 = fmaf(h, Wconv2[0 * 32 + o], y0);
        y1 = fmaf(h, Wconv2[1 * 32 + o], y1);
        y2 = fmaf(h, Wconv2[2 * 32 + o], y2);
        y3 = fmaf(h, Wconv2[3 * 32 + o], y3);
    }
    out[idx * 2]                   = y0;
    out[idx * 2 + 1]               = y1;
    out[BB * NN * 2 + idx * 2]     = y2;
    out[BB * NN * 2 + idx * 2 + 1] = y3;
}

extern "C" void kernel_launch(void* const* d_in, const int* in_sizes, int n_in,
                              void* d_out, int out_size)
{
    const float* t      = (const float*)d_in[0];
    const float* coors  = (const float*)d_in[1];
    const float* vel    = (const float*)d_in[2];
    const float* We1    = (const float*)d_in[3];
    const float* be1    = (const float*)d_in[4];
    const float* We2    = (const float*)d_in[5];
    const float* be2    = (const float*)d_in[6];
    const float* Wc1    = (const float*)d_in[7];
    const float* bc1    = (const float*)d_in[8];
    const float* Wc2    = (const float*)d_in[9];
    const float* bc2    = (const float*)d_in[10];
    const float* Wv     = (const float*)d_in[11];
    const float* bv     = (const float*)d_in[12];
    const float* Wconv1 = (const float*)d_in[13];
    const float* bconv1 = (const float*)d_in[14];
    const float* Wconv2 = (const float*)d_in[15];
    const float* bconv2 = (const float*)d_in[16];
    float* out = (float*)d_out;

    float *c0, *v0, *c1, *v1;
    cudaGetSymbolAddress((void**)&c0, g_c0);
    cudaGetSymbolAddress((void**)&v0, g_v0);
    cudaGetSymbolAddress((void**)&c1, g_c1);
    cudaGetSymbolAddress((void**)&v1, g_v1);

    dim3 grid(BB * 32);   // 2048 blocks: (batch, group of 4 i's)
    dim3 blk(128);
    egnn_layer_kernel<<<grid, blk>>>(t, coors, vel, c0, v0,
                                     We1, be1, We2, be2, Wc1, bc1, Wc2, bc2,
                                     Wv, bv, 0);
    egnn_layer_kernel<<<grid, blk>>>(t, c0, v0, c1, v1,
                                     We1, be1, We2, be2, Wc1, bc1, Wc2, bc2,
                                     Wv, bv, 1);
    egnn_head_kernel<<<(BB * NN + 127) / 128, 128>>>(c1, v1, Wconv1, bconv1,
                                                     Wconv2, bconv2, out);
}

// round 8
// speedup vs baseline: 2.2656x; 1.4210x over previous
#include <cuda_runtime.h>
#include <cuda_fp16.h>
#include <math.h>
#include <cstdint>

#define BB 64
#define NN 128
#define QPAD 65   // u32 words per channel row in s_q (padding kills bank collapse)

// scratch for intermediate coors/vel between layers (no allocs allowed)
__device__ float g_c0[BB*NN*2];
__device__ float g_v0[BB*NN*2];
__device__ float g_c1[BB*NN*2];
__device__ float g_v1[BB*NN*2];

union F2U { float2 f; unsigned long long u; };

__device__ __forceinline__ float2 ffma2(float2 a, float2 b, float2 c) {
    F2U A, B, C, R;
    A.f = a; B.f = b; C.f = c;
    asm("fma.rn.f32x2 %0, %1, %2, %3;" : "=l"(R.u) : "l"(A.u), "l"(B.u), "l"(C.u));
    return R.f;
}
__device__ __forceinline__ float2 fmul2(float2 a, float2 b) {
    F2U A, B, R;
    A.f = a; B.f = b;
    asm("mul.rn.f32x2 %0, %1, %2;" : "=l"(R.u) : "l"(A.u), "l"(B.u));
    return R.f;
}
__device__ __forceinline__ float2 fadd2(float2 a, float2 b) {
    F2U A, B, R;
    A.f = a; B.f = b;
    asm("add.rn.f32x2 %0, %1, %2;" : "=l"(R.u) : "l"(A.u), "l"(B.u));
    return R.f;
}

__device__ __forceinline__ float tanhaf(float x) {
    float r; asm("tanh.approx.f32 %0, %1;" : "=f"(r) : "f"(x)); return r;
}

// input h = x/2 (accumulated with pre-scaled weights). returns silu(x) = h + h*tanh(h).
__device__ __forceinline__ float2 silu2_pre(float2 h) {
    float t0 = tanhaf(h.x);
    float t1 = tanhaf(h.y);
    return ffma2(h, make_float2(t0, t1), h);
}
__device__ __forceinline__ float2 silu2(float2 x) {
    float2 h = fmul2(x, make_float2(0.5f, 0.5f));
    return silu2_pre(h);
}

__device__ __forceinline__ float seluf(float x) {
    const float scale = 1.0507009873554805f;
    const float alpha = 1.6732632423543772f;
    return x > 0.0f ? scale * x : scale * alpha * expm1f(x);
}

__device__ __forceinline__ uint32_t prmtb(uint32_t a, uint32_t b, uint32_t sel) {
    uint32_t d;
    asm("prmt.b32 %0, %1, %2, %3;" : "=r"(d) : "r"(a), "r"(b), "r"(sel));
    return d;
}
__device__ __forceinline__ uint32_t pack_h2(float2 v) {
    __half2 h = __floats2half2_rn(v.x, v.y);   // low half = v.x
    union { __half2 h; uint32_t u; } c; c.h = h;
    return c.u;
}
__device__ __forceinline__ uint32_t pack_h2s(float a, float b) {
    __half2 h = __floats2half2_rn(a, b);
    union { __half2 h; uint32_t u; } c; c.h = h;
    return c.u;
}

__device__ __forceinline__ void mma16816(float& d0, float& d1, float& d2, float& d3,
                                         uint32_t a0, uint32_t a1, uint32_t a2, uint32_t a3,
                                         uint32_t b0, uint32_t b1) {
    asm("mma.sync.aligned.m16n8k16.row.col.f32.f16.f16.f32 "
        "{%0,%1,%2,%3}, {%4,%5,%6,%7}, {%8,%9}, {%10,%11,%12,%13};"
        : "=f"(d0), "=f"(d1), "=f"(d2), "=f"(d3)
        : "r"(a0), "r"(a1), "r"(a2), "r"(a3), "r"(b0), "r"(b1),
          "f"(0.0f), "f"(0.0f), "f"(0.0f), "f"(0.0f));
}

__global__ __launch_bounds__(128, 4)
void egnn_layer_kernel(const float* __restrict__ t,
                       const float* __restrict__ cin,
                       const float* __restrict__ vin,
                       float* __restrict__ cout,
                       float* __restrict__ vout,
                       const float* __restrict__ We1,
                       const float* __restrict__ be1,
                       const float* __restrict__ We2,
                       const float* __restrict__ be2,
                       const float* __restrict__ Wc1,
                       const float* __restrict__ bc1,
                       const float* __restrict__ Wc2,
                       const float* __restrict__ bc2,
                       const float* __restrict__ Wv,
                       const float* __restrict__ bv,
                       int l)
{
    // block = (batch b, 4 i's). warp w owns i = ibase + w (all 128 j-edges).
    // q-phase: thread ln handles edge pairs A=(2ln, 2ln+1), B=(64+2ln, 64+2ln+1) in f32x2.
    // MLP3: tensor cores (mma.m16n8k16 f16), D consumed from fragments.
    __shared__ float4 sUV[16];        // {u,u,v,v} folded We1 (x0.5)
    __shared__ float4 sWC[16];        // {w,w,c,c} (x0.5, c includes be1)
    __shared__ float2 sbe2[16];       // dup be2 (x0.5)
    __shared__ float4 sWe2d[128];     // We2 dup pairs (x0.5)
    __shared__ float  sWc1raw[1024];  // 0.5*Wc1, k-major [k*64+n]
    __shared__ float4 sbcw[32];       // [cp] = {0.5*bc1[2cp], Wc2[2cp], 0.5*bc1[2cp+1], Wc2[2cp+1]}
    __shared__ float2 scj2[NN];
    __shared__ float  stj[NN];
    __shared__ uint32_t s_q[4 * 16 * QPAD];   // per-warp q tiles, f16x2 [ch][edge-pair]

    const int tid   = threadIdx.x;
    const int wid   = tid >> 5;
    const int ln    = tid & 31;
    const int bb    = blockIdx.x >> 5;
    const int ibase = (blockIdx.x & 31) * 4;
    const int i     = ibase + wid;

    // ---- staging ----
    const float* we1 = We1 + l * 128;
    if (tid < 16) {
        float u = 0.5f * (we1[tid] + we1[16 + tid] + we1[32 + tid]);
        float v = 0.5f * (we1[48 + tid] + we1[64 + tid] + we1[80 + tid]);
        float w = 0.5f * we1[96 + tid];
        float c = 0.5f * (we1[112 + tid] + be1[l * 16 + tid]);
        sUV[tid] = make_float4(u, u, v, v);
        sWC[tid] = make_float4(w, w, c, c);
        float b2 = 0.5f * be2[l * 16 + tid];
        sbe2[tid] = make_float2(b2, b2);
    } else if (tid < 48) {
        int k = tid - 16;
        sbcw[k] = make_float4(0.5f * bc1[l * 64 + 2 * k],     Wc2[l * 64 + 2 * k],
                              0.5f * bc1[l * 64 + 2 * k + 1], Wc2[l * 64 + 2 * k + 1]);
    }
    {
        int n = tid >> 3, cp = tid & 7;
        float a = 0.5f * We2[l * 256 + n * 16 + 2 * cp];
        float b = 0.5f * We2[l * 256 + n * 16 + 2 * cp + 1];
        sWe2d[tid] = make_float4(a, a, b, b);
    }
    #pragma unroll
    for (int idx = tid; idx < 1024; idx += 128)
        sWc1raw[idx] = 0.5f * Wc1[l * 1024 + idx];
    {
        const float2* c2 = (const float2*)(cin + bb * NN * 2);
        scj2[tid] = c2[tid];
        stj[tid]  = t[bb * NN + tid];
    }
    __syncthreads();

    const int e0 = 2 * ln;          // pair A
    const int e2 = 64 + 2 * ln;     // pair B
    const float ti  = stj[i];
    const float2 ci = scj2[i];
    const float2 ti2 = make_float2(ti, ti);

    // ---- q-phase: layer1 + MLP2 (f32, joint over pairs A/B, K-split) ----
    float2 q_a[16], q_b[16];
    {
        const float2 tjA = *(const float2*)&stj[e0];
        const float2 tjB = *(const float2*)&stj[e2];
        const float4 cjA = *(const float4*)&scj2[e0];
        const float4 cjB = *(const float4*)&scj2[e2];
        float2 dxA = make_float2(ci.x - cjA.x, ci.x - cjA.z);
        float2 dyA = make_float2(ci.y - cjA.y, ci.y - cjA.w);
        float2 dxB = make_float2(ci.x - cjB.x, ci.x - cjB.z);
        float2 dyB = make_float2(ci.y - cjB.y, ci.y - cjB.w);
        const float2 d2A = ffma2(dxA, dxA, fmul2(dyA, dyA));
        const float2 d2B = ffma2(dxB, dxB, fmul2(dyB, dyB));

        #pragma unroll
        for (int c = 0; c < 16; ++c) { q_a[c] = sbe2[c]; q_b[c] = sbe2[c]; }

        #pragma unroll
        for (int hk = 0; hk < 2; ++hk) {
            float2 x1a[8], x1b[8];
            #pragma unroll
            for (int k = 0; k < 8; ++k) {
                float4 uv = sUV[hk * 8 + k];
                float4 wc = sWC[hk * 8 + k];
                float2 bt = ffma2(ti2, make_float2(uv.x, uv.y),
                                  make_float2(wc.z, wc.w));
                float2 ha = ffma2(tjA, make_float2(uv.z, uv.w),
                           ffma2(d2A, make_float2(wc.x, wc.y), bt));
                float2 hb = ffma2(tjB, make_float2(uv.z, uv.w),
                           ffma2(d2B, make_float2(wc.x, wc.y), bt));
                x1a[k] = silu2_pre(ha);
                x1b[k] = silu2_pre(hb);
            }
            #pragma unroll
            for (int cp = 0; cp < 8; ++cp) {
                float2 a0 = q_a[2 * cp], a1 = q_a[2 * cp + 1];
                float2 b0 = q_b[2 * cp], b1 = q_b[2 * cp + 1];
                #pragma unroll
                for (int n = 0; n < 8; ++n) {
                    float4 w = sWe2d[(hk * 8 + n) * 8 + cp];
                    float2 wlo = make_float2(w.x, w.y);
                    float2 whi = make_float2(w.z, w.w);
                    a0 = ffma2(x1a[n], wlo, a0);
                    a1 = ffma2(x1a[n], whi, a1);
                    b0 = ffma2(x1b[n], wlo, b0);
                    b1 = ffma2(x1b[n], whi, b1);
                }
                q_a[2 * cp] = a0; q_a[2 * cp + 1] = a1;
                q_b[2 * cp] = b0; q_b[2 * cp + 1] = b1;
            }
        }
    }

    // ---- convert q to f16x2, stage to shared [ch][edge-pair] (stride QPAD) ----
    uint32_t* sq = s_q + wid * 16 * QPAD;
    #pragma unroll
    for (int c = 0; c < 16; ++c) {
        float2 qa = silu2(silu2_pre(q_a[c]));
        float2 qb = silu2(silu2_pre(q_b[c]));
        sq[c * QPAD + ln]      = pack_h2(qa);   // low half = even edge
        sq[c * QPAD + 32 + ln] = pack_h2(qb);
    }
    __syncwarp();

    // ---- B fragments (0.5*Wc1 f16), persistent: 8 n-tiles x 2 regs ----
    const int p = ln & 3;         // thread group column
    const int g = ln >> 2;        // group id (0..7)
    uint32_t bf0[8], bf1[8];
    #pragma unroll
    for (int nt = 0; nt < 8; ++nt) {
        int col = nt * 8 + g;
        bf0[nt] = pack_h2s(sWc1raw[(2 * p) * 64 + col],     sWc1raw[(2 * p + 1) * 64 + col]);
        bf1[nt] = pack_h2s(sWc1raw[(2 * p + 8) * 64 + col], sWc1raw[(2 * p + 9) * 64 + col]);
    }

    // ---- MLP3 via mma + in-register epilogue ----
    const uint32_t sel = ((ln >> 2) & 1) ? 0x7632u : 0x5410u;  // pick edge parity halves
    const float bc2l = bc2[l];
    float ax = 0.0f, ay = 0.0f;
    float wsum_bias = 0.0f;  // accumulate count of bc2 separately: wsum = partial + bc2

    #pragma unroll
    for (int r = 0; r < 8; ++r) {
        // A fragment: rows E=16r+g, E+8; k-cols 2p,2p+1 (+8)
        const int pe = 8 * r + (ln >> 3);
        uint32_t a0 = prmtb(sq[(2 * p) * QPAD + pe],     sq[(2 * p + 1) * QPAD + pe],     sel);
        uint32_t a1 = prmtb(sq[(2 * p) * QPAD + pe + 4], sq[(2 * p + 1) * QPAD + pe + 4], sel);
        uint32_t a2 = prmtb(sq[(2 * p + 8) * QPAD + pe],     sq[(2 * p + 9) * QPAD + pe],     sel);
        uint32_t a3 = prmtb(sq[(2 * p + 8) * QPAD + pe + 4], sq[(2 * p + 9) * QPAD + pe + 4], sel);

        float2 rs_lo = make_float2(0.0f, 0.0f);   // row E partial (this lane's col family)
        float2 rs_hi = make_float2(0.0f, 0.0f);   // row E+8
        #pragma unroll
        for (int nt = 0; nt < 8; ++nt) {
            float d0, d1, d2, d3;
            mma16816(d0, d1, d2, d3, a0, a1, a2, a3, bf0[nt], bf1[nt]);
            float4 bw = sbcw[4 * nt + p];
            float2 bias = make_float2(bw.x, bw.z);
            float2 wc   = make_float2(bw.y, bw.w);
            rs_lo = ffma2(silu2_pre(fadd2(make_float2(d0, d1), bias)), wc, rs_lo);
            rs_hi = ffma2(silu2_pre(fadd2(make_float2(d2, d3), bias)), wc, rs_hi);
        }
        // combine col halves + reduce over the 4 lanes sharing these rows
        float sE  = rs_lo.x + rs_lo.y;
        float sE8 = rs_hi.x + rs_hi.y;
        sE  += __shfl_xor_sync(0xFFFFFFFFu, sE, 1);
        sE  += __shfl_xor_sync(0xFFFFFFFFu, sE, 2);
        sE8 += __shfl_xor_sync(0xFFFFFFFFu, sE8, 1);
        sE8 += __shfl_xor_sync(0xFFFFFFFFu, sE8, 2);
        sE  += bc2l;
        sE8 += bc2l;
        // agg contribution (all 4 lanes duplicate; fixed by 0.25 at the end)
        const int E = 16 * r + g;
        float2 cjE  = scj2[E];
        float2 cjE8 = scj2[E + 8];
        ax += sE * (ci.x - cjE.x) + sE8 * (ci.x - cjE8.x);
        ay += sE * (ci.y - cjE.y) + sE8 * (ci.y - cjE8.y);
        (void)wsum_bias;
    }

    // ---- warp reduce + node update ----
    #pragma unroll
    for (int off = 16; off > 0; off >>= 1) {
        ax += __shfl_down_sync(0xFFFFFFFFu, ax, off);
        ay += __shfl_down_sync(0xFFFFFFFFu, ay, off);
    }
    if (ln == 0) {
        float AX = ax * 0.25f;
        float AY = ay * 0.25f;
        float wv  = Wv[l * 3] + Wv[l * 3 + 1] + Wv[l * 3 + 2];
        float phi = fmaf(ti, wv, bv[l]);
        float vx = vin[(bb * NN + i) * 2];
        float vy = vin[(bb * NN + i) * 2 + 1];
        float nvx = fmaf(phi, vx, AX);
        float nvy = fmaf(phi, vy, AY);
        float ncx = ci.x + nvx;
        float ncy = ci.y + nvy;
        cout[(bb * NN + i) * 2]     = seluf(ncx);
        cout[(bb * NN + i) * 2 + 1] = seluf(ncy);
        vout[(bb * NN + i) * 2]     = seluf(nvx);
        vout[(bb * NN + i) * 2 + 1] = seluf(nvy);
    }
}

__global__ void egnn_head_kernel(const float* __restrict__ cin,
                                 const float* __restrict__ vin,
                                 const float* __restrict__ Wconv1,
                                 const float* __restrict__ bconv1,
                                 const float* __restrict__ Wconv2,
                                 const float* __restrict__ bconv2,
                                 float* __restrict__ out)
{
    int idx = blockIdx.x * blockDim.x + threadIdx.x;
    if (idx >= BB * NN) return;

    float x0 = seluf(cin[idx * 2]);
    float x1 = seluf(cin[idx * 2 + 1]);
    float x2 = seluf(vin[idx * 2]);
    float x3 = seluf(vin[idx * 2 + 1]);

    float y0 = bconv2[0], y1 = bconv2[1], y2 = bconv2[2], y3 = bconv2[3];
    #pragma unroll
    for (int o = 0; o < 32; o++) {
        float h = bconv1[o];
        h = fmaf(x0, Wconv1[o * 4 + 0], h);
        h = fmaf(x1, Wconv1[o * 4 + 1], h);
        h = fmaf(x2, Wconv1[o * 4 + 2], h);
        h = fmaf(x3, Wconv1[o * 4 + 3], h);
        h = seluf(h);
        y0 = fmaf(h, Wconv2[0 * 32 + o], y0);
        y1 = fmaf(h, Wconv2[1 * 32 + o], y1);
        y2 = fmaf(h, Wconv2[2 * 32 + o], y2);
        y3 = fmaf(h, Wconv2[3 * 32 + o], y3);
    }
    out[idx * 2]                   = y0;
    out[idx * 2 + 1]               = y1;
    out[BB * NN * 2 + idx * 2]     = y2;
    out[BB * NN * 2 + idx * 2 + 1] = y3;
}

extern "C" void kernel_launch(void* const* d_in, const int* in_sizes, int n_in,
                              void* d_out, int out_size)
{
    const float* t      = (const float*)d_in[0];
    const float* coors  = (const float*)d_in[1];
    const float* vel    = (const float*)d_in[2];
    const float* We1    = (const float*)d_in[3];
    const float* be1    = (const float*)d_in[4];
    const float* We2    = (const float*)d_in[5];
    const float* be2    = (const float*)d_in[6];
    const float* Wc1    = (const float*)d_in[7];
    const float* bc1    = (const float*)d_in[8];
    const float* Wc2    = (const float*)d_in[9];
    const float* bc2    = (const float*)d_in[10];
    const float* Wv     = (const float*)d_in[11];
    const float* bv     = (const float*)d_in[12];
    const float* Wconv1 = (const float*)d_in[13];
    const float* bconv1 = (const float*)d_in[14];
    const float* Wconv2 = (const float*)d_in[15];
    const float* bconv2 = (const float*)d_in[16];
    float* out = (float*)d_out;

    float *c0, *v0, *c1, *v1;
    cudaGetSymbolAddress((void**)&c0, g_c0);
    cudaGetSymbolAddress((void**)&v0, g_v0);
    cudaGetSymbolAddress((void**)&c1, g_c1);
    cudaGetSymbolAddress((void**)&v1, g_v1);

    dim3 grid(BB * 32);   // 2048 blocks: (batch, group of 4 i's), warp-per-i
    dim3 blk(128);
    egnn_layer_kernel<<<grid, blk>>>(t, coors, vel, c0, v0,
                                     We1, be1, We2, be2, Wc1, bc1, Wc2, bc2,
                                     Wv, bv, 0);
    egnn_layer_kernel<<<grid, blk>>>(t, c0, v0, c1, v1,
                                     We1, be1, We2, be2, Wc1, bc1, Wc2, bc2,
                                     Wv, bv, 1);
    egnn_head_kernel<<<(BB * NN + 127) / 128, 128>>>(c1, v1, Wconv1, bconv1,
                                                     Wconv2, bconv2, out);
}

// round 9
// speedup vs baseline: 2.8259x; 1.2473x over previous
#include <cuda_runtime.h>
#include <cuda_fp16.h>
#include <math.h>
#include <cstdint>

#define BB 64
#define NN 128
#define XS 9   // words per edge row in s_x1 (stride padding)

// scratch for intermediate coors/vel between layers (no allocs allowed)
__device__ float g_c0[BB*NN*2];
__device__ float g_v0[BB*NN*2];
__device__ float g_c1[BB*NN*2];
__device__ float g_v1[BB*NN*2];

union F2U { float2 f; unsigned long long u; };

__device__ __forceinline__ float2 ffma2(float2 a, float2 b, float2 c) {
    F2U A, B, C, R;
    A.f = a; B.f = b; C.f = c;
    asm("fma.rn.f32x2 %0, %1, %2, %3;" : "=l"(R.u) : "l"(A.u), "l"(B.u), "l"(C.u));
    return R.f;
}
__device__ __forceinline__ float2 fmul2(float2 a, float2 b) {
    F2U A, B, R;
    A.f = a; B.f = b;
    asm("mul.rn.f32x2 %0, %1, %2;" : "=l"(R.u) : "l"(A.u), "l"(B.u));
    return R.f;
}

__device__ __forceinline__ float tanhaf(float x) {
    float r; asm("tanh.approx.f32 %0, %1;" : "=f"(r) : "f"(x)); return r;
}
// input h = x/2. returns silu(x) = h + h*tanh(h).
__device__ __forceinline__ float2 silu2_pre(float2 h) {
    float t0 = tanhaf(h.x);
    float t1 = tanhaf(h.y);
    return ffma2(h, make_float2(t0, t1), h);
}
__device__ __forceinline__ float2 silu2(float2 x) {
    float2 h = fmul2(x, make_float2(0.5f, 0.5f));
    return silu2_pre(h);
}
__device__ __forceinline__ float seluf(float x) {
    const float scale = 1.0507009873554805f;
    const float alpha = 1.6732632423543772f;
    return x > 0.0f ? scale * x : scale * alpha * expm1f(x);
}

__device__ __forceinline__ uint32_t pack_h2(float2 v) {
    __half2 h = __floats2half2_rn(v.x, v.y);   // low half = v.x
    union { __half2 h; uint32_t u; } c; c.h = h;
    return c.u;
}
__device__ __forceinline__ uint32_t pack_h2s(float a, float b) {
    __half2 h = __floats2half2_rn(a, b);
    union { __half2 h; uint32_t u; } c; c.h = h;
    return c.u;
}

// mma.m16n8k16 with C operand (bias folding)
__device__ __forceinline__ void mma16816c(float& d0, float& d1, float& d2, float& d3,
                                          uint32_t a0, uint32_t a1, uint32_t a2, uint32_t a3,
                                          uint32_t b0, uint32_t b1,
                                          float c0, float c1, float c2, float c3) {
    asm("mma.sync.aligned.m16n8k16.row.col.f32.f16.f16.f32 "
        "{%0,%1,%2,%3}, {%4,%5,%6,%7}, {%8,%9}, {%10,%11,%12,%13};"
        : "=f"(d0), "=f"(d1), "=f"(d2), "=f"(d3)
        : "r"(a0), "r"(a1), "r"(a2), "r"(a3), "r"(b0), "r"(b1),
          "f"(c0), "f"(c1), "f"(c2), "f"(c3));
}

__global__ __launch_bounds__(128, 5)
void egnn_layer_kernel(const float* __restrict__ t,
                       const float* __restrict__ cin,
                       const float* __restrict__ vin,
                       float* __restrict__ cout,
                       float* __restrict__ vout,
                       const float* __restrict__ We1,
                       const float* __restrict__ be1,
                       const float* __restrict__ We2,
                       const float* __restrict__ be2,
                       const float* __restrict__ Wc1,
                       const float* __restrict__ bc1,
                       const float* __restrict__ Wc2,
                       const float* __restrict__ bc2,
                       const float* __restrict__ Wv,
                       const float* __restrict__ bv,
                       int l)
{
    // block = (batch, 4 i's). warp w owns i = ibase + w (all 128 j-edges).
    // phase1: x1 (f32 layer1 + silu) -> f16 edge-major shared.
    // phase2: per 16-edge tile: MLP2 mma -> q (in-register silu + repack) -> MLP3 mma
    //         -> h silu + Wc2 dot (in-register) -> agg.
    __shared__ float4 sUVp[8];        // {u2c,u2c1,v2c,v2c1} x0.5
    __shared__ float4 sWCp[8];        // {w2c,w2c1,(c+be1)2c,(c+be1)2c1} x0.5
    __shared__ float2 sbe2p[8];       // {0.5be2[2c],0.5be2[2c+1]}
    __shared__ float  sWe2raw[256];   // 0.5*We2 [k*16+n]
    __shared__ float  sWc1raw[1024];  // 0.5*Wc1 [k*64+n]
    __shared__ float4 sbw3[32];       // [c]={0.5bc1[2c],0.5bc1[2c+1],Wc2[2c],Wc2[2c+1]}
    __shared__ float2 scj2[NN];
    __shared__ float  stj[NN];
    __shared__ uint32_t s_x1[4 * NN * XS];   // per-warp x1 tiles, f16x2 [edge][k-pair]

    const int tid   = threadIdx.x;
    const int wid   = tid >> 5;
    const int ln    = tid & 31;
    const int bb    = blockIdx.x >> 5;
    const int ibase = (blockIdx.x & 31) * 4;
    const int i     = ibase + wid;

    // ---- staging ----
    const float* we1 = We1 + l * 128;
    if (tid < 8) {
        int c0 = 2 * tid, c1 = 2 * tid + 1;
        float u0 = 0.5f * (we1[c0] + we1[16 + c0] + we1[32 + c0]);
        float u1 = 0.5f * (we1[c1] + we1[16 + c1] + we1[32 + c1]);
        float v0 = 0.5f * (we1[48 + c0] + we1[64 + c0] + we1[80 + c0]);
        float v1 = 0.5f * (we1[48 + c1] + we1[64 + c1] + we1[80 + c1]);
        float w0 = 0.5f * we1[96 + c0];
        float w1 = 0.5f * we1[96 + c1];
        float k0 = 0.5f * (we1[112 + c0] + be1[l * 16 + c0]);
        float k1 = 0.5f * (we1[112 + c1] + be1[l * 16 + c1]);
        sUVp[tid] = make_float4(u0, u1, v0, v1);
        sWCp[tid] = make_float4(w0, w1, k0, k1);
        sbe2p[tid] = make_float2(0.5f * be2[l * 16 + c0], 0.5f * be2[l * 16 + c1]);
    } else if (tid < 40) {
        int k = tid - 8;
        sbw3[k] = make_float4(0.5f * bc1[l * 64 + 2 * k], 0.5f * bc1[l * 64 + 2 * k + 1],
                              Wc2[l * 64 + 2 * k],        Wc2[l * 64 + 2 * k + 1]);
    }
    #pragma unroll
    for (int idx = tid; idx < 256; idx += 128)
        sWe2raw[idx] = 0.5f * We2[l * 256 + idx];
    #pragma unroll
    for (int idx = tid; idx < 1024; idx += 128)
        sWc1raw[idx] = 0.5f * Wc1[l * 1024 + idx];
    {
        const float2* c2 = (const float2*)(cin + bb * NN * 2);
        scj2[tid] = c2[tid];
        stj[tid]  = t[bb * NN + tid];
    }
    __syncthreads();

    const float ti  = stj[i];
    const float2 ci = scj2[i];
    const float2 ti2 = make_float2(ti, ti);

    // ---- persistent B fragments ----
    const int p = ln & 3;         // k-pair / col-pair group
    const int g = ln >> 2;        // row / col id (0..7)
    uint32_t b2f0[2], b2f1[2];    // We2 (0.5x) fragments, nt=0,1
    #pragma unroll
    for (int nt = 0; nt < 2; ++nt) {
        int col = nt * 8 + g;
        b2f0[nt] = pack_h2s(sWe2raw[(2 * p) * 16 + col],     sWe2raw[(2 * p + 1) * 16 + col]);
        b2f1[nt] = pack_h2s(sWe2raw[(2 * p + 8) * 16 + col], sWe2raw[(2 * p + 9) * 16 + col]);
    }
    uint32_t bf0[8], bf1[8];      // Wc1 (0.5x) fragments, nt=0..7
    #pragma unroll
    for (int nt = 0; nt < 8; ++nt) {
        int col = nt * 8 + g;
        bf0[nt] = pack_h2s(sWc1raw[(2 * p) * 64 + col],     sWc1raw[(2 * p + 1) * 64 + col]);
        bf1[nt] = pack_h2s(sWc1raw[(2 * p + 8) * 64 + col], sWc1raw[(2 * p + 9) * 64 + col]);
    }
    const float2 be2b0 = sbe2p[p];       // MLP2 C bias, nt0 (cols 2p,2p+1)
    const float2 be2b1 = sbe2p[p + 4];   // nt1 (cols 8+2p, 8+2p+1)

    // ---- phase 1: x1 for edges ln, ln+32, ln+64, ln+96 -> f16 edge-major ----
    uint32_t* sx = s_x1 + wid * NN * XS;
    #pragma unroll
    for (int ee = 0; ee < 4; ++ee) {
        const int e = ln + 32 * ee;
        const float tj = stj[e];
        const float2 cj = scj2[e];
        const float dx = ci.x - cj.x;
        const float dy = ci.y - cj.y;
        const float d = fmaf(dx, dx, dy * dy);
        const float2 tj2 = make_float2(tj, tj);
        const float2 d2  = make_float2(d, d);
        #pragma unroll
        for (int cp = 0; cp < 8; ++cp) {
            float4 uv = sUVp[cp];
            float4 wc = sWCp[cp];
            float2 h = ffma2(ti2, make_float2(uv.x, uv.y),
                      ffma2(tj2, make_float2(uv.z, uv.w),
                      ffma2(d2,  make_float2(wc.x, wc.y),
                                 make_float2(wc.z, wc.w))));
            sx[e * XS + cp] = pack_h2(silu2_pre(h));
        }
    }
    __syncwarp();

    // ---- phase 2: 8 tiles of 16 edges ----
    const float bc2l = bc2[l];
    float ax = 0.0f, ay = 0.0f;

    #pragma unroll
    for (int r = 0; r < 8; ++r) {
        const int elo = 16 * r + g;
        const int ehi = elo + 8;
        // A1 fragment (x1)
        uint32_t a0 = sx[elo * XS + p];
        uint32_t a1 = sx[ehi * XS + p];
        uint32_t a2 = sx[elo * XS + p + 4];
        uint32_t a3 = sx[ehi * XS + p + 4];

        // MLP2: q = silu(silu(x1 @ We2 + be2)); D chains into MLP3 A fragments
        uint32_t qa0, qa1, qa2, qa3;
        {
            float d0, d1, d2, d3;
            mma16816c(d0, d1, d2, d3, a0, a1, a2, a3, b2f0[0], b2f1[0],
                      be2b0.x, be2b0.y, be2b0.x, be2b0.y);
            qa0 = pack_h2(silu2(silu2_pre(make_float2(d0, d1))));
            qa1 = pack_h2(silu2(silu2_pre(make_float2(d2, d3))));
            mma16816c(d0, d1, d2, d3, a0, a1, a2, a3, b2f0[1], b2f1[1],
                      be2b1.x, be2b1.y, be2b1.x, be2b1.y);
            qa2 = pack_h2(silu2(silu2_pre(make_float2(d0, d1))));
            qa3 = pack_h2(silu2(silu2_pre(make_float2(d2, d3))));
        }

        // MLP3: h = silu(q @ Wc1 + bc1) (bias in C, weights pre-scaled 0.5)
        float2 rs_lo = make_float2(0.0f, 0.0f);
        float2 rs_hi = make_float2(0.0f, 0.0f);
        #pragma unroll
        for (int nt = 0; nt < 8; ++nt) {
            float4 bw = sbw3[4 * nt + p];
            float d0, d1, d2, d3;
            mma16816c(d0, d1, d2, d3, qa0, qa1, qa2, qa3, bf0[nt], bf1[nt],
                      bw.x, bw.y, bw.x, bw.y);
            float2 wc = make_float2(bw.z, bw.w);
            rs_lo = ffma2(silu2_pre(make_float2(d0, d1)), wc, rs_lo);
            rs_hi = ffma2(silu2_pre(make_float2(d2, d3)), wc, rs_hi);
        }
        float sE  = rs_lo.x + rs_lo.y;
        float sE8 = rs_hi.x + rs_hi.y;
        sE  += __shfl_xor_sync(0xFFFFFFFFu, sE, 1);
        sE  += __shfl_xor_sync(0xFFFFFFFFu, sE, 2);
        sE8 += __shfl_xor_sync(0xFFFFFFFFu, sE8, 1);
        sE8 += __shfl_xor_sync(0xFFFFFFFFu, sE8, 2);
        sE  += bc2l;
        sE8 += bc2l;
        // agg (4-lane duplication fixed by 0.25 at the end)
        float2 cjE  = scj2[elo];
        float2 cjE8 = scj2[ehi];
        ax += sE * (ci.x - cjE.x) + sE8 * (ci.x - cjE8.x);
        ay += sE * (ci.y - cjE.y) + sE8 * (ci.y - cjE8.y);
    }

    // ---- warp reduce + node update ----
    #pragma unroll
    for (int off = 16; off > 0; off >>= 1) {
        ax += __shfl_down_sync(0xFFFFFFFFu, ax, off);
        ay += __shfl_down_sync(0xFFFFFFFFu, ay, off);
    }
    if (ln == 0) {
        float AX = ax * 0.25f;
        float AY = ay * 0.25f;
        float wv  = Wv[l * 3] + Wv[l * 3 + 1] + Wv[l * 3 + 2];
        float phi = fmaf(ti, wv, bv[l]);
        float vx = vin[(bb * NN + i) * 2];
        float vy = vin[(bb * NN + i) * 2 + 1];
        float nvx = fmaf(phi, vx, AX);
        float nvy = fmaf(phi, vy, AY);
        float ncx = ci.x + nvx;
        float ncy = ci.y + nvy;
        cout[(bb * NN + i) * 2]     = seluf(ncx);
        cout[(bb * NN + i) * 2 + 1] = seluf(ncy);
        vout[(bb * NN + i) * 2]     = seluf(nvx);
        vout[(bb * NN + i) * 2 + 1] = seluf(nvy);
    }
}

__global__ void egnn_head_kernel(const float* __restrict__ cin,
                                 const float* __restrict__ vin,
                                 const float* __restrict__ Wconv1,
                                 const float* __restrict__ bconv1,
                                 const float* __restrict__ Wconv2,
                                 const float* __restrict__ bconv2,
                                 float* __restrict__ out)
{
    int idx = blockIdx.x * blockDim.x + threadIdx.x;
    if (idx >= BB * NN) return;

    float x0 = seluf(cin[idx * 2]);
    float x1 = seluf(cin[idx * 2 + 1]);
    float x2 = seluf(vin[idx * 2]);
    float x3 = seluf(vin[idx * 2 + 1]);

    float y0 = bconv2[0], y1 = bconv2[1], y2 = bconv2[2], y3 = bconv2[3];
    #pragma unroll
    for (int o = 0; o < 32; o++) {
        float h = bconv1[o];
        h = fmaf(x0, Wconv1[o * 4 + 0], h);
        h = fmaf(x1, Wconv1[o * 4 + 1], h);
        h = fmaf(x2, Wconv1[o * 4 + 2], h);
        h = fmaf(x3, Wconv1[o * 4 + 3], h);
        h = seluf(h);
        y0 = fmaf(h, Wconv2[0 * 32 + o], y0);
        y1 = fmaf(h, Wconv2[1 * 32 + o], y1);
        y2 = fmaf(h, Wconv2[2 * 32 + o], y2);
        y3 = fmaf(h, Wconv2[3 * 32 + o], y3);
    }
    out[idx * 2]                   = y0;
    out[idx * 2 + 1]               = y1;
    out[BB * NN * 2 + idx * 2]     = y2;
    out[BB * NN * 2 + idx * 2 + 1] = y3;
}

extern "C" void kernel_launch(void* const* d_in, const int* in_sizes, int n_in,
                              void* d_out, int out_size)
{
    const float* t      = (const float*)d_in[0];
    const float* coors  = (const float*)d_in[1];
    const float* vel    = (const float*)d_in[2];
    const float* We1    = (const float*)d_in[3];
    const float* be1    = (const float*)d_in[4];
    const float* We2    = (const float*)d_in[5];
    const float* be2    = (const float*)d_in[6];
    const float* Wc1    = (const float*)d_in[7];
    const float* bc1    = (const float*)d_in[8];
    const float* Wc2    = (const float*)d_in[9];
    const float* bc2    = (const float*)d_in[10];
    const float* Wv     = (const float*)d_in[11];
    const float* bv     = (const float*)d_in[12];
    const float* Wconv1 = (const float*)d_in[13];
    const float* bconv1 = (const float*)d_in[14];
    const float* Wconv2 = (const float*)d_in[15];
    const float* bconv2 = (const float*)d_in[16];
    float* out = (float*)d_out;

    float *c0, *v0, *c1, *v1;
    cudaGetSymbolAddress((void**)&c0, g_c0);
    cudaGetSymbolAddress((void**)&v0, g_v0);
    cudaGetSymbolAddress((void**)&c1, g_c1);
    cudaGetSymbolAddress((void**)&v1, g_v1);

    dim3 grid(BB * 32);   // 2048 blocks: (batch, group of 4 i's), warp-per-i
    dim3 blk(128);
    egnn_layer_kernel<<<grid, blk>>>(t, coors, vel, c0, v0,
                                     We1, be1, We2, be2, Wc1, bc1, Wc2, bc2,
                                     Wv, bv, 0);
    egnn_layer_kernel<<<grid, blk>>>(t, c0, v0, c1, v1,
                                     We1, be1, We2, be2, Wc1, bc1, Wc2, bc2,
                                     Wv, bv, 1);
    egnn_head_kernel<<<(BB * NN + 127) / 128, 128>>>(c1, v1, Wconv1, bconv1,
                                                     Wconv2, bconv2, out);
}